// round 15
// baseline (speedup 1.0000x reference)
#include <cuda_runtime.h>
#include <math.h>

#define NQ 6
#define NL 4
#define NA 4
#define PRE 64
#define NS 64

typedef unsigned long long u64;

// ---- compile-time CNOT permutation (scalar, foldable in device code) -------
__host__ __device__ __forceinline__ constexpr int cnot_map(int i, int c, int t) {
    return ((i >> c) & 1) ? (i ^ (1 << t)) : i;
}
__host__ __device__ __forceinline__ constexpr int perm_at(int l, int i) {
    int v = i;
    for (int ll = l; ll >= 0; --ll)
        for (int g = NQ - 1; g >= 0; --g)
            v = cnot_map(v, g, (g + 1) % NQ);
    return v;
}

// ---- ALL warp-uniform constants live in cbank (LDCU -> UR operands) --------
struct QConst {
    u64 W1p[PRE][NQ];     // (w,w) dup pairs, W1[k][q]
    u64 B1[PRE];          // (b1,b1)
    u64 W2p[PRE][NQ];     // (w/2, w/2) dup pairs (relu fold), W2[j][k] stored [k][j]
    u64 B2[NQ];           // (b2,b2)
    u64 T[NL * NQ];       // ( t,  t) per gate
    u64 N[NL * NQ];       // (-t, -t) per gate
    u64 Hw[NA + 1][NQ];   // (2*G2*w, dup)
    u64 Hb[NA + 1];       // (bias - G2*sumW*Tc, dup)
};
__constant__ QConst cq;

__device__ __forceinline__ u64 pk(float lo_, float hi_) {
    u64 r; asm("mov.b64 %0, {%1, %2};" : "=l"(r) : "f"(lo_), "f"(hi_)); return r;
}
__device__ __forceinline__ void upk(u64 v, float &lo_, float &hi_) {
    asm("mov.b64 {%0, %1}, %2;" : "=f"(lo_), "=f"(hi_) : "l"(v));
}
__device__ __forceinline__ u64 fma2(u64 a, u64 b, u64 c) {
    u64 d; asm("fma.rn.f32x2 %0, %1, %2, %3;" : "=l"(d) : "l"(a), "l"(b), "l"(c)); return d;
}
__device__ __forceinline__ u64 mul2(u64 a, u64 b) {
    u64 d; asm("mul.rn.f32x2 %0, %1, %2;" : "=l"(d) : "l"(a), "l"(b)); return d;
}
__device__ __forceinline__ u64 add2(u64 a, u64 b) {
    u64 d; asm("add.rn.f32x2 %0, %1, %2;" : "=l"(d) : "l"(a), "l"(b)); return d;
}
// relu(h) with /2 folded into W2: returns h + |h| ( == 2*relu(h), exact )
__device__ __forceinline__ u64 relu2x2(u64 h) {
    u64 a = h & 0x7FFFFFFF7FFFFFFFull;   // |.| per f32 lane
    return add2(h, a);
}

// ============================================================================
// Builder: writes ALL constants directly into cq's device backing storage.
// ============================================================================
__global__ void __launch_bounds__(256) build_consts(
    QConst* __restrict__ out,
    const float* __restrict__ qw,
    const float* __restrict__ W1, const float* __restrict__ b1,
    const float* __restrict__ W2, const float* __restrict__ b2,
    const float* __restrict__ Wp, const float* __restrict__ bp,
    const float* __restrict__ Wv, const float* __restrict__ bv)
{
    const int tid = threadIdx.x;
    __shared__ float sc[NL * NQ], stt[NL * NQ];
    __shared__ float sG2, sTc;

    for (int i = tid; i < PRE * NQ; i += 256) {
        int k = i / NQ, q = i % NQ;
        float w = W1[i];
        out->W1p[k][q] = pk(w, w);
        float w2 = 0.5f * W2[q * PRE + k];   // relu fold: /2
        out->W2p[k][q] = pk(w2, w2);
    }
    if (tid < PRE) { float v = b1[tid]; out->B1[tid] = pk(v, v); }
    if (tid < NQ)  { float v = b2[tid]; out->B2[tid] = pk(v, v); }

    if (tid < NL * NQ) {
        float s, c;
        sincosf(0.5f * qw[tid], &s, &c);
        float t = s / c;
        sc[tid] = c;
        stt[tid] = t;
        out->T[tid] = pk(t, t);
        out->N[tid] = pk(-t, -t);
    }
    __syncthreads();
    if (tid == 0) {
        float g = 1.0f, T = 1.0f;
#pragma unroll
        for (int i = 0; i < NL * NQ; ++i) {
            g *= sc[i];
            T *= 1.0f + stt[i] * stt[i];
        }
        sG2 = g * g;
        sTc = T;
    }
    __syncthreads();
    if (tid < (NA + 1) * NQ) {
        int r = tid / NQ, q = tid % NQ;
        float w = (r < NA) ? Wp[r * NQ + q] : Wv[q];
        float v = 2.0f * sG2 * w;
        out->Hw[r][q] = pk(v, v);
    }
    if (tid < NA + 1) {
        const float* Wr = (tid < NA) ? (Wp + tid * NQ) : Wv;
        float bias = (tid < NA) ? bp[tid] : bv[0];
        float rs = 0.0f;
#pragma unroll
        for (int q = 0; q < NQ; ++q) rs += Wr[q];
        float v = bias - sG2 * rs * sTc;
        out->Hb[tid] = pk(v, v);
    }
}

// ============================================================================
// Main kernel: 2 samples/thread (f32x2); uniform operands via cbank/UR;
// CNOTs folded into compile-time index permutations; no occupancy cap
// (140 regs natural — forcing 128 spills amplitudes, measured 2x slower).
// ============================================================================
__global__ void __launch_bounds__(64) qpolicy_kernel(
    const float* __restrict__ x,
    float* __restrict__ out_policy, float* __restrict__ out_value,
    int NT)   // NT = B/2
{
    const int t = blockIdx.x * 64 + threadIdx.x;
    if (t >= NT) return;

    // ---------------- load two samples --------------------------------------
    const float4* xr = reinterpret_cast<const float4*>(x + (size_t)t * 12);
    float4 v0 = xr[0], v1 = xr[1], v2 = xr[2];
    u64 XI[NQ];
    XI[0] = pk(v0.x, v1.z);
    XI[1] = pk(v0.y, v1.w);
    XI[2] = pk(v0.z, v2.x);
    XI[3] = pk(v0.w, v2.y);
    XI[4] = pk(v1.x, v2.z);
    XI[5] = pk(v1.y, v2.w);

    // ---------------- pre-net MLP (all weights via cbank -> UR) -------------
    u64 acc[NQ];
#pragma unroll
    for (int j = 0; j < NQ; ++j) acc[j] = cq.B2[j];

#pragma unroll
    for (int k = 0; k < PRE; ++k) {
        u64 h = cq.B1[k];
        h = fma2(cq.W1p[k][0], XI[0], h);
        h = fma2(cq.W1p[k][1], XI[1], h);
        h = fma2(cq.W1p[k][2], XI[2], h);
        h = fma2(cq.W1p[k][3], XI[3], h);
        h = fma2(cq.W1p[k][4], XI[4], h);
        h = fma2(cq.W1p[k][5], XI[5], h);
        h = relu2x2(h);                       // 2*relu(h); W2 pre-halved
        acc[0] = fma2(cq.W2p[k][0], h, acc[0]);
        acc[1] = fma2(cq.W2p[k][1], h, acc[1]);
        acc[2] = fma2(cq.W2p[k][2], h, acc[2]);
        acc[3] = fma2(cq.W2p[k][3], h, acc[3]);
        acc[4] = fma2(cq.W2p[k][4], h, acc[4]);
        acc[5] = fma2(cq.W2p[k][5], h, acc[5]);
    }

    // ---------------- angle embedding ---------------------------------------
    u64 ECP[NQ], ESP[NQ];
#pragma unroll
    for (int j = 0; j < NQ; ++j) {
        float a0, a1;
        upk(acc[j], a0, a1);
        a0 = fmaxf(a0, 0.0f);
        a1 = fmaxf(a1, 0.0f);
        float s0, c0, s1c, c1;
        __sincosf(0.5f * a0, &s0, &c0);
        __sincosf(0.5f * a1, &s1c, &c1);
        ECP[j] = pk(c0, c1);
        ESP[j] = pk(s0, s1c);
    }

    u64 P[NS];
    P[0] = ECP[0];
    P[1] = ESP[0];
#pragma unroll
    for (int q = 1; q < NQ; ++q) {
        const int sz = 1 << q;
#pragma unroll
        for (int i = 0; i < NS; ++i) {
            if (i < sz) {
                P[i | sz] = mul2(P[i], ESP[q]);
                P[i]      = mul2(P[i], ECP[q]);
            }
        }
    }

    // ---------------- 4 layers: RY through compile-time CNOT permutation ----
#pragma unroll
    for (int l = 0; l < NL; ++l) {
#pragma unroll
        for (int i = 0; i < NQ; ++i) {
            const int g = l * NQ + i;
            const u64 Tt = cq.T[g];
            const u64 Nt = cq.N[g];
            const int qb = 1 << i;
#pragma unroll
            for (int base = 0; base < NS; ++base) {
                if (!(base & qb)) {
                    const int pa = perm_at(l, base);
                    const int pb = perm_at(l, base | qb);
                    u64 A = P[pa];
                    u64 B = P[pb];
                    P[pa] = fma2(Nt, B, A);
                    P[pb] = fma2(Tt, A, B);
                }
            }
        }
    }

    // ---------------- measurement: square + marginal folds (logical frame) --
#pragma unroll
    for (int i = 0; i < NS; ++i) P[i] = mul2(P[i], P[i]);

    u64 F[NQ];
    u64 S[32];
    {
        u64 e0a, e0b;
        {
            u64 ev0 = P[perm_at(NL - 1, 0)], od0 = P[perm_at(NL - 1, 1)];
            u64 ev1 = P[perm_at(NL - 1, 2)], od1 = P[perm_at(NL - 1, 3)];
            e0a = ev0; e0b = ev1;
            S[0] = add2(ev0, od0);
            S[1] = add2(ev1, od1);
        }
#pragma unroll
        for (int i = 2; i < 32; ++i) {
            u64 ev = P[perm_at(NL - 1, 2 * i)], od = P[perm_at(NL - 1, 2 * i + 1)];
            if (i & 1) e0b = add2(e0b, ev); else e0a = add2(e0a, ev);
            S[i] = add2(ev, od);
        }
        F[0] = add2(e0a, e0b);
    }
    {
        u64 e1a = S[0], e1b = S[2];
#pragma unroll
        for (int i = 0; i < 16; ++i) {
            u64 ev = S[2 * i], od = S[2 * i + 1];
            if (i >= 2) {
                if (i & 1) e1b = add2(e1b, ev); else e1a = add2(e1a, ev);
            }
            S[i] = add2(ev, od);
        }
        F[1] = add2(e1a, e1b);
    }
    {
        u64 e2 = S[0];
#pragma unroll
        for (int i = 0; i < 8; ++i) {
            u64 ev = S[2 * i], od = S[2 * i + 1];
            if (i >= 1) e2 = add2(e2, ev);
            S[i] = add2(ev, od);
        }
        F[2] = e2;
    }
    {
        u64 e3 = S[0];
#pragma unroll
        for (int i = 0; i < 4; ++i) {
            u64 ev = S[2 * i], od = S[2 * i + 1];
            if (i >= 1) e3 = add2(e3, ev);
            S[i] = add2(ev, od);
        }
        F[3] = e3;
    }
    F[4] = add2(S[0], S[2]);
    F[5] = add2(S[0], S[1]);

    // ---------------- heads (constants -> UR) -------------------------------
    u64 L[NA + 1];
#pragma unroll
    for (int r = 0; r < NA + 1; ++r) {
        u64 a = cq.Hb[r];
#pragma unroll
        for (int q = 0; q < NQ; ++q)
            a = fma2(cq.Hw[r][q], F[q], a);
        L[r] = a;
    }
    float l0[NA], l1[NA];
#pragma unroll
    for (int a = 0; a < NA; ++a) upk(L[a], l0[a], l1[a]);

    {
        float m = fmaxf(fmaxf(l0[0], l0[1]), fmaxf(l0[2], l0[3]));
        float e0 = __expf(l0[0] - m), e1 = __expf(l0[1] - m);
        float e2 = __expf(l0[2] - m), e3 = __expf(l0[3] - m);
        float inv = __fdividef(1.0f, e0 + e1 + e2 + e3);
        reinterpret_cast<float4*>(out_policy)[2 * t] =
            make_float4(e0 * inv, e1 * inv, e2 * inv, e3 * inv);
    }
    {
        float m = fmaxf(fmaxf(l1[0], l1[1]), fmaxf(l1[2], l1[3]));
        float e0 = __expf(l1[0] - m), e1 = __expf(l1[1] - m);
        float e2 = __expf(l1[2] - m), e3 = __expf(l1[3] - m);
        float inv = __fdividef(1.0f, e0 + e1 + e2 + e3);
        reinterpret_cast<float4*>(out_policy)[2 * t + 1] =
            make_float4(e0 * inv, e1 * inv, e2 * inv, e3 * inv);
    }

    float va, vb; upk(L[NA], va, vb);
    reinterpret_cast<float2*>(out_value)[t] = make_float2(va, vb);
}

extern "C" void kernel_launch(void* const* d_in, const int* in_sizes, int n_in,
                              void* d_out, int out_size) {
    const float* x  = (const float*)d_in[0];
    const float* W1 = (const float*)d_in[1];
    const float* b1 = (const float*)d_in[2];
    const float* W2 = (const float*)d_in[3];
    const float* b2 = (const float*)d_in[4];
    const float* qw = (const float*)d_in[5];
    const float* Wp = (const float*)d_in[6];
    const float* bp = (const float*)d_in[7];
    const float* Wv = (const float*)d_in[8];
    const float* bv = (const float*)d_in[9];

    const int B  = in_sizes[0] / NQ;
    const int NT = B / 2;
    float* out_policy = (float*)d_out;
    float* out_value  = (float*)d_out + (size_t)B * NA;

    void* cq_ptr = nullptr;
    cudaGetSymbolAddress(&cq_ptr, cq);
    build_consts<<<1, 256>>>((QConst*)cq_ptr, qw, W1, b1, W2, b2, Wp, bp, Wv, bv);

    const int threads = 64;
    const int blocks = (NT + threads - 1) / threads;
    qpolicy_kernel<<<blocks, threads>>>(x, out_policy, out_value, NT);
}

// round 16
// speedup vs baseline: 1.1335x; 1.1335x over previous
#include <cuda_runtime.h>
#include <math.h>

#define NQ 6
#define NL 4
#define NA 4
#define PRE 64
#define NS 64

typedef unsigned long long u64;

// ---- ALL warp-uniform constants live in cbank (LDCU -> UR operands) --------
struct QConst {
    u64 W1p[PRE][NQ];     // (w,w) dup pairs, W1[k][q]
    u64 B1[PRE];          // (b1,b1)
    u64 W2p[PRE][NQ];     // (w,w) dup pairs, W2[j][k] stored [k][j]
    u64 B2[NQ];           // (b2,b2)
    u64 T[NL * NQ];       // ( t,  t) per gate
    u64 N[NL * NQ];       // (-t, -t) per gate
    u64 Hw[NA + 1][NQ];   // (2*G2*w, dup)
    u64 Hb[NA + 1];       // (bias - G2*sumW*Tc, dup)
};
__constant__ QConst cq;

__device__ __forceinline__ u64 pk(float lo_, float hi_) {
    u64 r; asm("mov.b64 %0, {%1, %2};" : "=l"(r) : "f"(lo_), "f"(hi_)); return r;
}
__device__ __forceinline__ void upk(u64 v, float &lo_, float &hi_) {
    asm("mov.b64 {%0, %1}, %2;" : "=f"(lo_), "=f"(hi_) : "l"(v));
}
__device__ __forceinline__ u64 fma2(u64 a, u64 b, u64 c) {
    u64 d; asm("fma.rn.f32x2 %0, %1, %2, %3;" : "=l"(d) : "l"(a), "l"(b), "l"(c)); return d;
}
__device__ __forceinline__ u64 mul2(u64 a, u64 b) {
    u64 d; asm("mul.rn.f32x2 %0, %1, %2;" : "=l"(d) : "l"(a), "l"(b)); return d;
}
__device__ __forceinline__ u64 add2(u64 a, u64 b) {
    u64 d; asm("add.rn.f32x2 %0, %1, %2;" : "=l"(d) : "l"(a), "l"(b)); return d;
}
__device__ __forceinline__ u64 relu2(u64 v) {
    float a, b; upk(v, a, b);
    return pk(fmaxf(a, 0.0f), fmaxf(b, 0.0f));
}

// ============================================================================
// Builder: writes ALL constants directly into cq's device backing storage.
// ============================================================================
__global__ void __launch_bounds__(256) build_consts(
    QConst* __restrict__ out,
    const float* __restrict__ qw,
    const float* __restrict__ W1, const float* __restrict__ b1,
    const float* __restrict__ W2, const float* __restrict__ b2,
    const float* __restrict__ Wp, const float* __restrict__ bp,
    const float* __restrict__ Wv, const float* __restrict__ bv)
{
    const int tid = threadIdx.x;
    __shared__ float sc[NL * NQ], stt[NL * NQ];
    __shared__ float sG2, sTc;

    for (int i = tid; i < PRE * NQ; i += 256) {
        int k = i / NQ, q = i % NQ;
        float w = W1[i];
        out->W1p[k][q] = pk(w, w);
        float w2 = W2[q * PRE + k];
        out->W2p[k][q] = pk(w2, w2);
    }
    if (tid < PRE) { float v = b1[tid]; out->B1[tid] = pk(v, v); }
    if (tid < NQ)  { float v = b2[tid]; out->B2[tid] = pk(v, v); }

    if (tid < NL * NQ) {
        float s, c;
        sincosf(0.5f * qw[tid], &s, &c);
        float t = s / c;
        sc[tid] = c;
        stt[tid] = t;
        out->T[tid] = pk(t, t);
        out->N[tid] = pk(-t, -t);
    }
    __syncthreads();
    if (tid == 0) {
        float g = 1.0f, T = 1.0f;
#pragma unroll
        for (int i = 0; i < NL * NQ; ++i) {
            g *= sc[i];
            T *= 1.0f + stt[i] * stt[i];
        }
        sG2 = g * g;
        sTc = T;
    }
    __syncthreads();
    if (tid < (NA + 1) * NQ) {
        int r = tid / NQ, q = tid % NQ;
        float w = (r < NA) ? Wp[r * NQ + q] : Wv[q];
        float v = 2.0f * sG2 * w;
        out->Hw[r][q] = pk(v, v);
    }
    if (tid < NA + 1) {
        const float* Wr = (tid < NA) ? (Wp + tid * NQ) : Wv;
        float bias = (tid < NA) ? bp[tid] : bv[0];
        float rs = 0.0f;
#pragma unroll
        for (int q = 0; q < NQ; ++q) rs += Wr[q];
        float v = bias - sG2 * rs * sTc;
        out->Hb[tid] = pk(v, v);
    }
}

// ============================================================================
// Main kernel: 2 samples/thread (f32x2); ALL uniform operands from cbank/UR.
// No shared memory, no block-level sync. 140 regs natural (no cap — forcing
// 128 spills amplitudes; measured 2x slower in R6/R14).
// ============================================================================
__global__ void __launch_bounds__(64) qpolicy_kernel(
    const float* __restrict__ x,
    float* __restrict__ out_policy, float* __restrict__ out_value,
    int NT)   // NT = B/2
{
    const int t = blockIdx.x * 64 + threadIdx.x;
    if (t >= NT) return;

    // ---------------- load two samples --------------------------------------
    const float4* xr = reinterpret_cast<const float4*>(x + (size_t)t * 12);
    float4 v0 = xr[0], v1 = xr[1], v2 = xr[2];
    u64 XI[NQ];
    XI[0] = pk(v0.x, v1.z);
    XI[1] = pk(v0.y, v1.w);
    XI[2] = pk(v0.z, v2.x);
    XI[3] = pk(v0.w, v2.y);
    XI[4] = pk(v1.x, v2.z);
    XI[5] = pk(v1.y, v2.w);

    // ---------------- pre-net MLP (all weights via cbank -> UR) -------------
    u64 acc[NQ];
#pragma unroll
    for (int j = 0; j < NQ; ++j) acc[j] = cq.B2[j];

#pragma unroll
    for (int k = 0; k < PRE; ++k) {
        u64 h = cq.B1[k];
        h = fma2(cq.W1p[k][0], XI[0], h);
        h = fma2(cq.W1p[k][1], XI[1], h);
        h = fma2(cq.W1p[k][2], XI[2], h);
        h = fma2(cq.W1p[k][3], XI[3], h);
        h = fma2(cq.W1p[k][4], XI[4], h);
        h = fma2(cq.W1p[k][5], XI[5], h);
        h = relu2(h);
        acc[0] = fma2(cq.W2p[k][0], h, acc[0]);
        acc[1] = fma2(cq.W2p[k][1], h, acc[1]);
        acc[2] = fma2(cq.W2p[k][2], h, acc[2]);
        acc[3] = fma2(cq.W2p[k][3], h, acc[3]);
        acc[4] = fma2(cq.W2p[k][4], h, acc[4]);
        acc[5] = fma2(cq.W2p[k][5], h, acc[5]);
    }

    // ---------------- angle embedding ---------------------------------------
    u64 ECP[NQ], ESP[NQ];
#pragma unroll
    for (int j = 0; j < NQ; ++j) {
        float a0, a1;
        upk(relu2(acc[j]), a0, a1);
        float s0, c0, s1c, c1;
        __sincosf(0.5f * a0, &s0, &c0);
        __sincosf(0.5f * a1, &s1c, &c1);
        ECP[j] = pk(c0, c1);
        ESP[j] = pk(s0, s1c);
    }

    u64 P[NS];
    P[0] = ECP[0];
    P[1] = ESP[0];
#pragma unroll
    for (int q = 1; q < NQ; ++q) {
        const int sz = 1 << q;
#pragma unroll
        for (int i = 0; i < NS; ++i) {
            if (i < sz) {
                P[i | sz] = mul2(P[i], ESP[q]);
                P[i]      = mul2(P[i], ECP[q]);
            }
        }
    }

    // ---------------- 4 layers: CNOT renames + tan RY (consts -> UR) --------
#pragma unroll
    for (int l = 0; l < NL; ++l) {
#pragma unroll
        for (int i = 0; i < NQ; ++i) {
            const int cb = 1 << i;
            const int tb = 1 << ((i + 1) % NQ);
#pragma unroll
            for (int idx = 0; idx < NS; ++idx) {
                if ((idx & cb) && !(idx & tb)) {
                    u64 tmp = P[idx];
                    P[idx] = P[idx | tb];
                    P[idx | tb] = tmp;
                }
            }
        }
#pragma unroll
        for (int i = 0; i < NQ; ++i) {
            const int g = l * NQ + i;
            const u64 Tt = cq.T[g];
            const u64 Nt = cq.N[g];
            const int qb = 1 << i;
#pragma unroll
            for (int base = 0; base < NS; ++base) {
                if (!(base & qb)) {
                    u64 A = P[base];
                    u64 B = P[base | qb];
                    P[base]      = fma2(Nt, B, A);
                    P[base | qb] = fma2(Tt, A, B);
                }
            }
        }
    }

    // ---------------- measurement (in place) --------------------------------
#pragma unroll
    for (int i = 0; i < NS; ++i) P[i] = mul2(P[i], P[i]);

    u64 F[NQ];
    {
        u64 e0a = P[0], e0b = P[2];
#pragma unroll
        for (int i = 0; i < 32; ++i) {
            u64 ev = P[2 * i], od = P[2 * i + 1];
            if (i >= 2) {
                if (i & 1) e0b = add2(e0b, ev); else e0a = add2(e0a, ev);
            }
            P[i] = add2(ev, od);
        }
        F[0] = add2(e0a, e0b);
    }
    {
        u64 e1a = P[0], e1b = P[2];
#pragma unroll
        for (int i = 0; i < 16; ++i) {
            u64 ev = P[2 * i], od = P[2 * i + 1];
            if (i >= 2) {
                if (i & 1) e1b = add2(e1b, ev); else e1a = add2(e1a, ev);
            }
            P[i] = add2(ev, od);
        }
        F[1] = add2(e1a, e1b);
    }
    {
        u64 e2 = P[0];
#pragma unroll
        for (int i = 0; i < 8; ++i) {
            u64 ev = P[2 * i], od = P[2 * i + 1];
            if (i >= 1) e2 = add2(e2, ev);
            P[i] = add2(ev, od);
        }
        F[2] = e2;
    }
    {
        u64 e3 = P[0];
#pragma unroll
        for (int i = 0; i < 4; ++i) {
            u64 ev = P[2 * i], od = P[2 * i + 1];
            if (i >= 1) e3 = add2(e3, ev);
            P[i] = add2(ev, od);
        }
        F[3] = e3;
    }
    F[4] = add2(P[0], P[2]);
    F[5] = add2(P[0], P[1]);

    // ---------------- heads (constants -> UR) -------------------------------
    u64 L[NA + 1];
#pragma unroll
    for (int r = 0; r < NA + 1; ++r) {
        u64 a = cq.Hb[r];
#pragma unroll
        for (int q = 0; q < NQ; ++q)
            a = fma2(cq.Hw[r][q], F[q], a);
        L[r] = a;
    }
    float l0[NA], l1[NA];
#pragma unroll
    for (int a = 0; a < NA; ++a) upk(L[a], l0[a], l1[a]);

    {
        float m = fmaxf(fmaxf(l0[0], l0[1]), fmaxf(l0[2], l0[3]));
        float e0 = __expf(l0[0] - m), e1 = __expf(l0[1] - m);
        float e2 = __expf(l0[2] - m), e3 = __expf(l0[3] - m);
        float inv = __fdividef(1.0f, e0 + e1 + e2 + e3);
        reinterpret_cast<float4*>(out_policy)[2 * t] =
            make_float4(e0 * inv, e1 * inv, e2 * inv, e3 * inv);
    }
    {
        float m = fmaxf(fmaxf(l1[0], l1[1]), fmaxf(l1[2], l1[3]));
        float e0 = __expf(l1[0] - m), e1 = __expf(l1[1] - m);
        float e2 = __expf(l1[2] - m), e3 = __expf(l1[3] - m);
        float inv = __fdividef(1.0f, e0 + e1 + e2 + e3);
        reinterpret_cast<float4*>(out_policy)[2 * t + 1] =
            make_float4(e0 * inv, e1 * inv, e2 * inv, e3 * inv);
    }

    float va, vb; upk(L[NA], va, vb);
    reinterpret_cast<float2*>(out_value)[t] = make_float2(va, vb);
}

extern "C" void kernel_launch(void* const* d_in, const int* in_sizes, int n_in,
                              void* d_out, int out_size) {
    const float* x  = (const float*)d_in[0];
    const float* W1 = (const float*)d_in[1];
    const float* b1 = (const float*)d_in[2];
    const float* W2 = (const float*)d_in[3];
    const float* b2 = (const float*)d_in[4];
    const float* qw = (const float*)d_in[5];
    const float* Wp = (const float*)d_in[6];
    const float* bp = (const float*)d_in[7];
    const float* Wv = (const float*)d_in[8];
    const float* bv = (const float*)d_in[9];

    const int B  = in_sizes[0] / NQ;
    const int NT = B / 2;
    float* out_policy = (float*)d_out;
    float* out_value  = (float*)d_out + (size_t)B * NA;

    void* cq_ptr = nullptr;
    cudaGetSymbolAddress(&cq_ptr, cq);
    build_consts<<<1, 256>>>((QConst*)cq_ptr, qw, W1, b1, W2, b2, Wp, bp, Wv, bv);

    const int threads = 64;
    const int blocks = (NT + threads - 1) / threads;
    qpolicy_kernel<<<blocks, threads>>>(x, out_policy, out_value, NT);
}